// round 1
// baseline (speedup 1.0000x reference)
#include <cuda_runtime.h>
#include <math.h>
#include <float.h>

#define BB 1024
#define TT 512
#define KK 48
#define NEGV (-10000.0f)
#define TAG_START 46
#define TAG_STOP 47
#define NB 8                       // batches per CTA in main kernel
#define MAIN_THREADS (NB * KK)     // 384 threads = 12 warps

// ---- device scratch (no allocations allowed) ----
__device__ float        g_gold[BB];
__device__ int          g_bestlast[BB];
__device__ unsigned int g_bpw[(size_t)BB * (TT / 4) * KK];  // packed backpointers, 4 steps/word

// ============================================================
// Kernel 1: gold path score per batch
// gold[b] = sum_t feats[b,t,tag_t] + trans[tag_t, prev_t]  + trans[STOP, tag_{T-1}]
// (tags never hit masked entries, so raw trans is correct)
// ============================================================
__global__ void gold_kernel(const float* __restrict__ feats,
                            const float* __restrict__ trans,
                            const int* __restrict__ tags) {
    int b = blockIdx.x;
    int tid = threadIdx.x;
    __shared__ float red[256];
    const int*   tg = tags + (size_t)b * TT;
    const float* f  = feats + (size_t)b * TT * KK;

    float s = 0.f;
    for (int t = tid; t < TT; t += 256) {
        int tag  = tg[t];
        int prev = (t == 0) ? TAG_START : tg[t - 1];
        s += f[(size_t)t * KK + tag] + trans[tag * KK + prev];
    }
    red[tid] = s;
    __syncthreads();
    for (int off = 128; off > 0; off >>= 1) {
        if (tid < off) red[tid] += red[tid + off];
        __syncthreads();
    }
    if (tid == 0) {
        g_gold[b] = red[0] + trans[TAG_STOP * KK + tg[TT - 1]];
    }
}

// ============================================================
// Kernel 2: fused forward (log-partition) + Viterbi recurrence.
// Layout: 8 groups x 48 threads; group g owns batch blockIdx.x*8+g,
// thread nx within group owns "next" tag nx.
// Forward via exp-factorization: alpha'[n] = emit + m + log(sum_p e[p]*M[n,p]),
// e[p] = exp(alpha[p]-m), M = exp(trans) held in registers.
// Viterbi uses the exact same fp ops as the reference (bit-exact paths).
// ============================================================
__global__ void __launch_bounds__(MAIN_THREADS)
crf_main_kernel(const float* __restrict__ feats,
                const float* __restrict__ trans,
                float* __restrict__ out) {
    __shared__ __align__(16) float trans_sh[KK * 49];      // pitch 49 (not used in hot loop)
    __shared__ __align__(16) float e_sh[2][NB][KK];        // double buffered
    __shared__ __align__(16) float v_sh[2][NB][KK];

    int tid = threadIdx.x;
    int g   = tid / KK;        // group = local batch
    int nx  = tid - g * KK;    // "next" tag index
    int b   = blockIdx.x * NB + g;

    // masked transitions into shared: trans[next, prev]; no INTO start, no OUT of stop
    for (int i = tid; i < KK * KK; i += MAIN_THREADS) {
        int r = i / KK, c = i - r * KK;
        float tv = trans[i];
        if (r == TAG_START || c == TAG_STOP) tv = NEGV;
        trans_sh[r * 49 + c] = tv;
    }
    __syncthreads();

    // per-thread register copies of this next-row
    float Mrow[KK], trow[KK];
#pragma unroll
    for (int p = 0; p < KK; p++) {
        float tv = trans_sh[nx * 49 + p];
        trow[p] = tv;
        Mrow[p] = (tv <= -9000.f) ? 0.f : __expf(tv);
    }

    float alpha = (nx == TAG_START) ? 0.f : NEGV;
    float v     = alpha;
    float m     = 0.f;   // current rescale reference (init max alpha = 0)

    const float* fp = feats + (size_t)b * TT * KK + nx;
    float emit_cur = fp[0];

    unsigned int bpacc = 0;
    unsigned int* bpp = g_bpw + (size_t)b * (TT / 4) * KK + nx;

    for (int t = 0; t < TT; t++) {
        int par = t & 1;
        // prefetch next step's emission
        float emit_nxt = (t + 1 < TT) ? fp[(size_t)(t + 1) * KK] : 0.f;

        e_sh[par][g][nx] = __expf(alpha - m);
        v_sh[par][g][nx] = v;
        __syncthreads();   // single barrier per step (double-buffered smem)

        float a0 = 0.f, a1 = 0.f, a2 = 0.f, a3 = 0.f;
        float best = -FLT_MAX;
        int bpv = 0;
#pragma unroll
        for (int p0 = 0; p0 < KK; p0 += 4) {
            float4 e4 = *reinterpret_cast<const float4*>(&e_sh[par][g][p0]);
            float4 v4 = *reinterpret_cast<const float4*>(&v_sh[par][g][p0]);
            a0 = fmaf(e4.x, Mrow[p0 + 0], a0);
            a1 = fmaf(e4.y, Mrow[p0 + 1], a1);
            a2 = fmaf(e4.z, Mrow[p0 + 2], a2);
            a3 = fmaf(e4.w, Mrow[p0 + 3], a3);
            // Viterbi: ascending scan, strict '>' => first-max (matches jnp.argmax)
            float s0 = v4.x + trow[p0 + 0];
            bool c0 = s0 > best; best = c0 ? s0 : best; bpv = c0 ? (p0 + 0) : bpv;
            float s1 = v4.y + trow[p0 + 1];
            bool c1 = s1 > best; best = c1 ? s1 : best; bpv = c1 ? (p0 + 1) : bpv;
            float s2 = v4.z + trow[p0 + 2];
            bool c2 = s2 > best; best = c2 ? s2 : best; bpv = c2 ? (p0 + 2) : bpv;
            float s3 = v4.w + trow[p0 + 3];
            bool c3 = s3 > best; best = c3 ? s3 : best; bpv = c3 ? (p0 + 3) : bpv;
        }
        float acc = (a0 + a1) + (a2 + a3);

        float emit = emit_cur;
        emit_cur = emit_nxt;

        alpha = emit + m + __logf(acc);   // may go -inf for START row: harmless (exp->0)
        v = best + emit;

        bpacc |= ((unsigned int)bpv) << ((t & 3) * 8);
        if ((t & 3) == 3) {
            bpp[(size_t)(t >> 2) * KK] = bpacc;
            bpacc = 0;
            // exact rescale: new m = old m + log(max e) = exact max of pre-step alpha.
            // e_sh[par] is still valid here (next overwrite of this buffer is at t+2,
            // gated behind the t+1 barrier which we haven't reached yet).
            float mx = -FLT_MAX;
#pragma unroll
            for (int p0 = 0; p0 < KK; p0 += 4) {
                float4 e4 = *reinterpret_cast<const float4*>(&e_sh[par][g][p0]);
                mx = fmaxf(mx, fmaxf(fmaxf(e4.x, e4.y), fmaxf(e4.z, e4.w)));
            }
            m = m + __logf(mx);
        } else {
            m += 12.f;  // safe upper bound on per-step alpha growth
        }
    }

    // ---- epilogue: logZ, path_score, best_last ----
    __syncthreads();
    e_sh[0][g][nx] = alpha + trans_sh[TAG_STOP * 49 + nx];
    v_sh[0][g][nx] = v + trans_sh[TAG_STOP * 49 + nx];
    __syncthreads();
    if (nx == 0) {
        float mx = -FLT_MAX;
        for (int k = 0; k < KK; k++) mx = fmaxf(mx, e_sh[0][g][k]);
        float s = 0.f;
        for (int k = 0; k < KK; k++) s += __expf(e_sh[0][g][k] - mx);
        float logZ = mx + __logf(s);
        out[b] = logZ - g_gold[b];                 // nll

        float bv = -FLT_MAX;
        int bi = 0;
        for (int k = 0; k < KK; k++) {
            float tv = v_sh[0][g][k];
            if (tv > bv) { bv = tv; bi = k; }      // first-max
        }
        out[BB + b] = bv;                          // path_score
        g_bestlast[b] = bi;
    }
}

// ============================================================
// Kernel 3: backtrack. Stage the batch's packed backpointers into
// shared (24 KB), then walk the 512-step chain at LDS latency.
// ============================================================
__global__ void backtrack_kernel(float* __restrict__ out) {
    int b = blockIdx.x;
    int tid = threadIdx.x;
    __shared__ __align__(16) unsigned int bp_sh[(TT / 4) * KK];  // 6144 words
    __shared__ float path_sh[TT];

    const unsigned int* src = g_bpw + (size_t)b * (TT / 4) * KK;
    for (int i = tid; i < (TT / 4) * KK; i += blockDim.x)
        bp_sh[i] = src[i];
    __syncthreads();

    if (tid == 0) {
        int cur = g_bestlast[b];
        for (int t = TT - 1; t >= 0; t--) {
            path_sh[t] = (float)cur;
            unsigned int w = bp_sh[(t >> 2) * KK + cur];
            cur = (int)((w >> ((t & 3) * 8)) & 0xFFu);
        }
    }
    __syncthreads();

    float* dst = out + 2 * BB + (size_t)b * TT;
    for (int t = tid; t < TT; t += blockDim.x)
        dst[t] = path_sh[t];
}

// ============================================================
extern "C" void kernel_launch(void* const* d_in, const int* in_sizes, int n_in,
                              void* d_out, int out_size) {
    const float* feats = (const float*)d_in[0];
    const float* trans = (const float*)d_in[1];
    const int*   tags  = (const int*)d_in[2];
    float* out = (float*)d_out;

    gold_kernel<<<BB, 256>>>(feats, trans, tags);
    crf_main_kernel<<<BB / NB, MAIN_THREADS>>>(feats, trans, out);
    backtrack_kernel<<<BB, 128>>>(out);
}

// round 2
// speedup vs baseline: 1.0109x; 1.0109x over previous
#include <cuda_runtime.h>
#include <math.h>
#include <float.h>

#define BB 1024
#define TT 512
#define KK 48
#define NEGV (-10000.0f)
#define TAG_START 46
#define TAG_STOP 47
#define NB 8                        // batches per CTA
#define MAIN_THREADS (NB * KK * 2)  // 768: (batch, next, half)

// ---- device scratch (no allocations allowed) ----
__device__ int          g_bestlast[BB];
__device__ unsigned int g_bpw[(size_t)BB * (TT / 4) * KK];  // packed backpointers, 4 steps/word

// ============================================================
// Fused kernel: forward log-partition + Viterbi recurrence + gold score.
// Thread layout: tid = g*96 + nx*2 + h.
//   g  = local batch (0..7), nx = "next" tag (0..47), h = prev-half (0/1).
// Thread (nx,h) handles prevs [24h, 24h+24); partner = tid^1 (same warp).
// Forward: alpha'[n] = emit + m + log(sum_p e[p]*M[n,p]), e[p]=exp(alpha[p]-m),
//   M=exp(trans) in registers (24/thread). Viterbi uses the reference's exact
//   fp32 ops with first-max tie semantics (ascending scan + strict '>',
//   partner-combine prefers the lower-index chunk on exact tie).
// ============================================================
__global__ void __launch_bounds__(MAIN_THREADS)
crf_main_kernel(const float* __restrict__ feats,
                const float* __restrict__ trans,
                const int* __restrict__ tags,
                float* __restrict__ out) {
    __shared__ __align__(16) float trans_sh[KK * 49];   // masked, pitch 49
    __shared__ __align__(16) float e_sh[2][NB][KK];     // double buffered
    __shared__ __align__(16) float v_sh[2][NB][KK];
    __shared__ int tag_sh[NB][TT];                      // 16 KB

    int tid = threadIdx.x;
    int g   = tid / 96;          // local batch; warps never straddle g (96=3 warps)
    int r   = tid - g * 96;
    int nx  = r >> 1;            // "next" tag
    int h   = r & 1;             // prev-half
    int base = h * 24;
    int b   = blockIdx.x * NB + g;

    // masked transitions: trans[next, prev]; never INTO start, never OUT of stop
    for (int i = tid; i < KK * KK; i += MAIN_THREADS) {
        int rr = i / KK, cc = i - rr * KK;
        float tv = trans[i];
        if (rr == TAG_START || cc == TAG_STOP) tv = NEGV;
        trans_sh[rr * 49 + cc] = tv;
    }
    // stage tags for this CTA's 8 batches (coalesced; tags is [B][T] row-major)
    for (int i = tid; i < NB * TT; i += MAIN_THREADS)
        ((int*)tag_sh)[i] = tags[(size_t)blockIdx.x * NB * TT + i];
    __syncthreads();

    // per-thread register slice of this next-row (24 prevs)
    float Ms[24], ts[24];
#pragma unroll
    for (int j = 0; j < 24; j++) {
        float tv = trans_sh[nx * 49 + base + j];
        ts[j] = tv;
        Ms[j] = (tv <= -9000.f) ? 0.f : __expf(tv);
    }

    float alpha = (nx == TAG_START) ? 0.f : NEGV;
    float v     = alpha;
    float m     = 0.f;      // rescale reference (init max alpha = 0)
    float gold  = 0.f;
    int prevtag = TAG_START;

    const float* fp = feats + (size_t)b * TT * KK + nx;
    float emit_cur = fp[0];

    unsigned int bpacc = 0;
    unsigned int* bpp = g_bpw + (size_t)b * (TT / 4) * KK + nx;

    for (int t = 0; t < TT; t++) {
        int par = t & 1;
        float emit_nxt = (t + 1 < TT) ? fp[(size_t)(t + 1) * KK] : 0.f;

        if (h == 0) {
            e_sh[par][g][nx] = __expf(alpha - m);
            v_sh[par][g][nx] = v;
        }
        __syncthreads();     // single barrier per step (double-buffered smem)

        // gold accumulation: exactly one (nx==tag, h==0) thread per group per step
        int tagt = tag_sh[g][t];          // uniform per warp (broadcast)
        if (h == 0 && nx == tagt)
            gold += emit_cur + trans_sh[tagt * 49 + prevtag];
        prevtag = tagt;

        float a0 = 0.f, a1 = 0.f;
        float best = -FLT_MAX;
        int bpv = base;
#pragma unroll
        for (int j = 0; j < 24; j += 4) {
            float4 e4 = *reinterpret_cast<const float4*>(&e_sh[par][g][base + j]);
            float4 v4 = *reinterpret_cast<const float4*>(&v_sh[par][g][base + j]);
            a0 = fmaf(e4.x, Ms[j + 0], a0);
            a1 = fmaf(e4.y, Ms[j + 1], a1);
            a0 = fmaf(e4.z, Ms[j + 2], a0);
            a1 = fmaf(e4.w, Ms[j + 3], a1);
            // ascending scan, strict '>' => first-max (matches jnp.argmax)
            float s0 = v4.x + ts[j + 0];
            bool c0 = s0 > best; best = c0 ? s0 : best; bpv = c0 ? (base + j + 0) : bpv;
            float s1 = v4.y + ts[j + 1];
            bool c1 = s1 > best; best = c1 ? s1 : best; bpv = c1 ? (base + j + 1) : bpv;
            float s2 = v4.z + ts[j + 2];
            bool c2 = s2 > best; best = c2 ? s2 : best; bpv = c2 ? (base + j + 2) : bpv;
            float s3 = v4.w + ts[j + 3];
            bool c3 = s3 > best; best = c3 ? s3 : best; bpv = c3 ? (base + j + 3) : bpv;
        }
        float acc = a0 + a1;
        // partner combine (lane^1, always same warp). Disjoint index chunks:
        // on exact tie take the lower-index chunk's winner.
        acc += __shfl_xor_sync(0xFFFFFFFFu, acc, 1);
        float ob  = __shfl_xor_sync(0xFFFFFFFFu, best, 1);
        int   obp = __shfl_xor_sync(0xFFFFFFFFu, bpv, 1);
        bool take = (ob > best) || (ob == best && obp < bpv);
        best = take ? ob : best;
        bpv  = take ? obp : bpv;

        float emit = emit_cur;
        emit_cur = emit_nxt;

        alpha = emit + m + __logf(acc);   // -inf on START row: harmless (exp->0)
        v = best + emit;

        if (h == 0) {
            bpacc |= ((unsigned int)bpv) << ((t & 3) * 8);
            if ((t & 3) == 3) {
                bpp[(size_t)(t >> 2) * KK] = bpacc;
                bpacc = 0;
            }
        }
        if ((t & 3) == 3) {
            // exact rescale: m += log(max e) == exact max of pre-step alpha.
            // e_sh[par] is still valid: its next overwrite (t+2's store) is
            // gated behind the t+1 barrier, which we haven't reached.
            float mx = -FLT_MAX;
#pragma unroll
            for (int p0 = 0; p0 < KK; p0 += 4) {
                float4 e4 = *reinterpret_cast<const float4*>(&e_sh[par][g][p0]);
                mx = fmaxf(mx, fmaxf(fmaxf(e4.x, e4.y), fmaxf(e4.z, e4.w)));
            }
            m = m + __logf(mx);
        } else {
            m += 12.f;  // safe upper bound on per-step alpha growth
        }
    }

    // ---- epilogue: logZ, path_score, best_last, gold reduce ----
    int tag_last = tag_sh[g][TT - 1];
    __syncthreads();
    if (h == 0) {
        e_sh[0][g][nx] = alpha + trans_sh[TAG_STOP * 49 + nx];
        v_sh[0][g][nx] = v + trans_sh[TAG_STOP * 49 + nx];
        e_sh[1][g][nx] = gold;
    }
    __syncthreads();
    if (r == 0) {   // nx==0 && h==0
        float mx = -FLT_MAX;
        for (int k = 0; k < KK; k++) mx = fmaxf(mx, e_sh[0][g][k]);
        float s = 0.f;
        for (int k = 0; k < KK; k++) s += __expf(e_sh[0][g][k] - mx);
        float logZ = mx + __logf(s);

        float gsum = 0.f;
        for (int k = 0; k < KK; k++) gsum += e_sh[1][g][k];
        gsum += trans_sh[TAG_STOP * 49 + tag_last];

        out[b] = logZ - gsum;                      // nll

        float bv = -FLT_MAX;
        int bi = 0;
        for (int k = 0; k < KK; k++) {
            float tv = v_sh[0][g][k];
            if (tv > bv) { bv = tv; bi = k; }      // first-max
        }
        out[BB + b] = bv;                          // path_score
        g_bestlast[b] = bi;
    }
}

// ============================================================
// Backtrack: stage the batch's packed backpointers into shared (24 KB),
// then walk the 512-step chain at LDS latency.
// ============================================================
__global__ void backtrack_kernel(float* __restrict__ out) {
    int b = blockIdx.x;
    int tid = threadIdx.x;
    __shared__ __align__(16) unsigned int bp_sh[(TT / 4) * KK];  // 6144 words
    __shared__ float path_sh[TT];

    const unsigned int* src = g_bpw + (size_t)b * (TT / 4) * KK;
    for (int i = tid; i < (TT / 4) * KK; i += blockDim.x)
        bp_sh[i] = src[i];
    __syncthreads();

    if (tid == 0) {
        int cur = g_bestlast[b];
        for (int t = TT - 1; t >= 0; t--) {
            path_sh[t] = (float)cur;
            unsigned int w = bp_sh[(t >> 2) * KK + cur];
            cur = (int)((w >> ((t & 3) * 8)) & 0xFFu);
        }
    }
    __syncthreads();

    float* dst = out + 2 * BB + (size_t)b * TT;
    for (int t = tid; t < TT; t += blockDim.x)
        dst[t] = path_sh[t];
}

// ============================================================
extern "C" void kernel_launch(void* const* d_in, const int* in_sizes, int n_in,
                              void* d_out, int out_size) {
    const float* feats = (const float*)d_in[0];
    const float* trans = (const float*)d_in[1];
    const int*   tags  = (const int*)d_in[2];
    float* out = (float*)d_out;

    crf_main_kernel<<<BB / NB, MAIN_THREADS>>>(feats, trans, tags, out);
    backtrack_kernel<<<BB, 128>>>(out);
}

// round 5
// speedup vs baseline: 1.6828x; 1.6646x over previous
#include <cuda_runtime.h>
#include <math.h>
#include <float.h>

#define BB 1024
#define TT 512
#define KK 48
#define NEGV (-10000.0f)
#define TAG_START 46
#define TAG_STOP 47
#define NB 4                        // batches per CTA
#define MAIN_THREADS (NB * 96)      // 384: (batch, next, half)

// ---- device scratch (no allocations allowed) ----
__device__ int   g_bestlast[BB];
__device__ float g_v[BB * TT * KK];   // per-step Viterbi value vectors (100 MB)

// f32x2 packed helpers (sm_103a; ptxas never auto-fuses these)
#define F32X2_FMA(d, a, b, c) \
    asm("fma.rn.f32x2 %0, %1, %2, %3;" : "=l"(d) : "l"(a), "l"(b), "l"(c))
#define F32X2_ADD(d, a, b) \
    asm("add.rn.f32x2 %0, %1, %2;" : "=l"(d) : "l"(a), "l"(b))
#define F32X2_UNPACK(lo, hi, x) \
    asm("mov.b64 {%0, %1}, %2;" : "=f"(lo), "=f"(hi) : "l"(x))
#define F32X2_PACK(d, lo, hi) \
    asm("mov.b64 %0, {%1, %2};" : "=l"(d) : "f"(lo), "f"(hi))

// ============================================================
// Fused kernel: forward log-partition + Viterbi max recurrence + gold score.
// tid = g*96 + nx*2 + h : g=local batch, nx=next tag, h=prev half.
// Thread handles prevs [24h, 24h+24); partner = lane^1 (same warp).
// No per-step argmax: the value vector v_t[48] is stored to g_v each step,
// and backpointers are recomputed along the winning path in backtrack_kernel
// (bit-exact: same inputs, same fp ops).
// Groups sync with per-batch named barriers (3 aligned warps each) so
// batches drift independently — no CTA-wide lockstep.
// ============================================================
__global__ void __launch_bounds__(MAIN_THREADS)
crf_main_kernel(const float* __restrict__ feats,
                const float* __restrict__ trans,
                const int* __restrict__ tags,
                float* __restrict__ out) {
    __shared__ float trans_sh[KK * 49];                 // masked, pitch 49
    __shared__ __align__(16) float e_sh[2][NB][KK];     // double buffered
    __shared__ __align__(16) float v_sh[2][NB][KK];
    __shared__ int tag_sh[NB][TT];

    int tid = threadIdx.x;
    int g   = tid / 96;          // group = 3 aligned warps
    int r   = tid - g * 96;
    int nx  = r >> 1;
    int h   = r & 1;
    int base = h * 24;
    int b   = blockIdx.x * NB + g;
    int barid = g + 1;           // named barrier per group (ids 1..NB)

    // masked transitions: trans[next, prev]; never INTO start, never OUT of stop
    for (int i = tid; i < KK * KK; i += MAIN_THREADS) {
        int rr = i / KK, cc = i - rr * KK;
        float tv = trans[i];
        if (rr == TAG_START || cc == TAG_STOP) tv = NEGV;
        trans_sh[rr * 49 + cc] = tv;
    }
    for (int i = tid; i < NB * TT; i += MAIN_THREADS)
        ((int*)tag_sh)[i] = tags[(size_t)blockIdx.x * NB * TT + i];
    __syncthreads();

    // packed register slices of this next-row (24 prevs -> 12 f32x2)
    unsigned long long Ms2[12], ts2[12];
#pragma unroll
    for (int j = 0; j < 12; j++) {
        float t0 = trans_sh[nx * 49 + base + 2 * j];
        float t1 = trans_sh[nx * 49 + base + 2 * j + 1];
        float M0 = (t0 <= -9000.f) ? 0.f : __expf(t0);
        float M1 = (t1 <= -9000.f) ? 0.f : __expf(t1);
        F32X2_PACK(ts2[j], t0, t1);
        F32X2_PACK(Ms2[j], M0, M1);
    }

    float alpha = (nx == TAG_START) ? 0.f : NEGV;
    float v     = alpha;
    float m     = 0.f;       // rescale reference
    float gold  = 0.f;
    int prevtag = TAG_START;

    const float* fp = feats + (size_t)b * TT * KK + nx;
    float emit_cur = fp[0];
    float* vout = g_v + (size_t)b * TT * KK + nx;

    for (int t = 0; t < TT; t++) {
        int par = t & 1;
        float emit_nxt = (t + 1 < TT) ? fp[(size_t)(t + 1) * KK] : 0.f;

        if (h == 0) {
            e_sh[par][g][nx] = __expf(alpha - m);
            v_sh[par][g][nx] = v;
            vout[(size_t)t * KK] = v;     // loop-top value vector for backtrack
        }
        asm volatile("bar.sync %0, 96;" :: "r"(barid));

        // gold: exactly one (nx==tag, h==0) thread per group per step
        int tagt = tag_sh[g][t];
        if (h == 0 && nx == tagt)
            gold += emit_cur + trans_sh[tagt * 49 + prevtag];
        prevtag = tagt;

        const ulonglong2* ep = (const ulonglong2*)&e_sh[par][g][base];
        const ulonglong2* vp = (const ulonglong2*)&v_sh[par][g][base];
        unsigned long long acc0 = 0ull, acc1 = 0ull;   // packed (+0,+0)
        float b0 = -FLT_MAX, b1 = -FLT_MAX;
#pragma unroll
        for (int j = 0; j < 6; j++) {
            ulonglong2 e2 = ep[j];
            ulonglong2 v2 = vp[j];
            F32X2_FMA(acc0, e2.x, Ms2[2 * j], acc0);
            F32X2_FMA(acc1, e2.y, Ms2[2 * j + 1], acc1);
            unsigned long long s01, s23;
            F32X2_ADD(s01, v2.x, ts2[2 * j]);
            F32X2_ADD(s23, v2.y, ts2[2 * j + 1]);
            float s0, s1, s2, s3;
            F32X2_UNPACK(s0, s1, s01);
            F32X2_UNPACK(s2, s3, s23);
            b0 = fmaxf(b0, s0); b1 = fmaxf(b1, s1);
            b0 = fmaxf(b0, s2); b1 = fmaxf(b1, s3);
        }
        float a0, a1, a2, a3;
        F32X2_UNPACK(a0, a1, acc0);
        F32X2_UNPACK(a2, a3, acc1);
        float acc = (a0 + a1) + (a2 + a3);
        float best = fmaxf(b0, b1);
        // partner combine (lane^1, same warp); max is exact either order
        acc += __shfl_xor_sync(0xFFFFFFFFu, acc, 1);
        best = fmaxf(best, __shfl_xor_sync(0xFFFFFFFFu, best, 1));

        float emit = emit_cur;
        emit_cur = emit_nxt;

        alpha = emit + m + __logf(acc);   // -inf on START row: harmless
        v = best + emit;

        if ((t & 3) == 3) {
            // exact rescale: m += log(max e). e_sh[par] still valid: its next
            // overwrite (step t+2's store) is gated behind step t+1's barrier.
            float mx = -FLT_MAX;
#pragma unroll
            for (int p0 = 0; p0 < KK; p0 += 4) {
                float4 e4 = *reinterpret_cast<const float4*>(&e_sh[par][g][p0]);
                mx = fmaxf(mx, fmaxf(fmaxf(e4.x, e4.y), fmaxf(e4.z, e4.w)));
            }
            m = m + __logf(mx);
        } else {
            m += 12.f;  // safe bound on per-step alpha growth
        }
    }

    // ---- epilogue: logZ, path_score, best_last, gold reduce ----
    asm volatile("bar.sync %0, 96;" :: "r"(barid));
    if (h == 0) {
        e_sh[0][g][nx] = alpha + trans_sh[TAG_STOP * 49 + nx];
        v_sh[0][g][nx] = v + trans_sh[TAG_STOP * 49 + nx];
        e_sh[1][g][nx] = gold;
    }
    asm volatile("bar.sync %0, 96;" :: "r"(barid));
    if (r == 0) {
        float mx = -FLT_MAX;
        for (int k = 0; k < KK; k++) mx = fmaxf(mx, e_sh[0][g][k]);
        float s = 0.f;
        for (int k = 0; k < KK; k++) s += __expf(e_sh[0][g][k] - mx);
        float logZ = mx + __logf(s);

        float gsum = 0.f;
        for (int k = 0; k < KK; k++) gsum += e_sh[1][g][k];
        gsum += trans_sh[TAG_STOP * 49 + tag_sh[g][TT - 1]];
        out[b] = logZ - gsum;                      // nll

        float bv = -FLT_MAX;
        int bi = 0;
        for (int k = 0; k < KK; k++) {
            float tv = v_sh[0][g][k];
            if (tv > bv) { bv = tv; bi = k; }      // first-max
        }
        out[BB + b] = bv;                          // path_score
        g_bestlast[b] = bi;
    }
}

// ============================================================
// Backtrack: one warp per batch. Recomputes bp_t[cur] =
// first-argmax_p (v_t[p] + trans[cur, p]) along the chosen path only.
// Bit-exact vs reference: identical FADD inputs; first-max via
// order-preserving int keys + redux.max + ballot/ffs (lowest index wins).
// v rows prefetched 8-deep (loads are cur-independent).
// ============================================================
__global__ void __launch_bounds__(256)
backtrack_kernel(const float* __restrict__ trans, float* __restrict__ out) {
    __shared__ float trans_sh[KK * 49];
    __shared__ float path_sh[8][TT];

    int tid = threadIdx.x;
    int w = tid >> 5, l = tid & 31;
    int b = blockIdx.x * 8 + w;

    for (int i = tid; i < KK * KK; i += 256) {
        int rr = i / KK, cc = i - rr * KK;
        float tv = trans[i];
        if (rr == TAG_START || cc == TAG_STOP) tv = NEGV;
        trans_sh[rr * 49 + cc] = tv;
    }
    __syncthreads();

    const float* vbase = g_v + (size_t)b * TT * KK;
    bool two = (l < 16);     // lanes 0..15 also own p = l+32

    float ca[8], cb[8], na[8], nb2[8];
#pragma unroll
    for (int i = 0; i < 8; i++) {
        int t = 511 - i;
        ca[i] = __ldg(&vbase[(size_t)t * KK + l]);
        nb2[i] = 0.f;
        cb[i] = two ? __ldg(&vbase[(size_t)t * KK + l + 32]) : 0.f;
    }

    int cur = g_bestlast[b];

    for (int c = 0; c < 64; c++) {
        int tb = 511 - c * 8;
        if (c < 63) {
#pragma unroll
            for (int i = 0; i < 8; i++) {
                int t = tb - 8 - i;
                na[i] = __ldg(&vbase[(size_t)t * KK + l]);
                nb2[i] = two ? __ldg(&vbase[(size_t)t * KK + l + 32]) : 0.f;
            }
        }
#pragma unroll
        for (int i = 0; i < 8; i++) {
            int t = tb - i;
            if (l == 0) path_sh[w][t] = (float)cur;
            // scores for this row
            float sa = ca[i] + trans_sh[cur * 49 + l];
            float sl = sa;
            int pl = l;
            if (two) {
                float sb = cb[i] + trans_sh[cur * 49 + l + 32];
                if (sb > sa) { sl = sb; pl = l + 32; }   // strict: lower idx wins tie
            }
            // order-preserving int key (no NaNs present)
            int u = __float_as_int(sl);
            int key = u ^ ((u >> 31) & 0x7FFFFFFF);
            int bk;
            asm("redux.sync.max.s32 %0, %1, 0xffffffff;" : "=r"(bk) : "r"(key));
            unsigned m0 = __ballot_sync(0xFFFFFFFFu, (key == bk) && (pl < 32));
            unsigned m1 = __ballot_sync(0xFFFFFFFFu, (key == bk));
            cur = m0 ? (__ffs(m0) - 1) : (__ffs(m1) - 1 + 32);
        }
        if (c < 63) {
#pragma unroll
            for (int i = 0; i < 8; i++) { ca[i] = na[i]; cb[i] = nb2[i]; }
        }
    }

    __syncwarp();
    float* dst = out + 2 * BB + (size_t)b * TT;
    for (int t = l; t < TT; t += 32)
        dst[t] = path_sh[w][t];
}

// ============================================================
extern "C" void kernel_launch(void* const* d_in, const int* in_sizes, int n_in,
                              void* d_out, int out_size) {
    const float* feats = (const float*)d_in[0];
    const float* trans = (const float*)d_in[1];
    const int*   tags  = (const int*)d_in[2];
    float* out = (float*)d_out;

    crf_main_kernel<<<BB / NB, MAIN_THREADS>>>(feats, trans, tags, out);
    backtrack_kernel<<<BB / 8, 256>>>(trans, out);
}